// round 8
// baseline (speedup 1.0000x reference)
#include <cuda_runtime.h>
#include <cuda_fp16.h>

#define HID   51
#define TT    2048
#define NN    1024
#define CHUNK 64
#define H2PAD 28          // half2 per h row (26 used + 2 zero pad) = 7 x 16B
#define NTHREADS 128      // 4 warps; worker tid<104: jA=tid>>2, g=tid&3

__device__ __forceinline__ float tanhx(float x) {
    float r; asm("tanh.approx.f32 %0, %1;" : "=f"(r) : "f"(x)); return r;
}

__global__ void __launch_bounds__(NTHREADS, 7)
lstm2_kernel(const float* __restrict__ stim,
             const float* __restrict__ Wih1,   // (204,1)
             const float* __restrict__ Whh1,   // (204,51)
             const float* __restrict__ bih1,
             const float* __restrict__ bhh1,
             const float* __restrict__ Wih2,   // (4,51)
             const float* __restrict__ Whh2,   // (4,1)
             const float* __restrict__ bih2,
             const float* __restrict__ bhh2,
             float* __restrict__ out)          // (1024,2048)
{
    __shared__ __align__(16) __half2 hbuf[2][H2PAD];   // h1 as fp16 pairs
    __shared__ __align__(16) float x_sh[CHUNK];
    __shared__ __align__(16) float ob_sh[CHUNK];       // y(t0+dt-1)
    __shared__ float h2_sh;                            // layer-2 h state

    const int tid  = threadIdx.x;
    const int wid  = tid >> 5;
    const int jA   = tid >> 2;         // 0..25 for workers
    const int g    = tid & 3;          // gate 0..3 (i,f,g,o)
    const int jB   = jA + 26;          // 26..51; 51 => layer-2
    const int n0   = blockIdx.x;       // one sequence per block
    const bool worker = (tid < 104);
    const bool isl2   = worker && (jB == HID);  // tid 100..103
    const bool g0     = (g == 0);
    const bool gg2    = (g == 2);      // tanh gate

    // ---- per-lane weights: two fp16 rows (52 regs) ----------------------
    __half2 whA[26], whB[26];
#pragma unroll
    for (int kk = 0; kk < 26; kk++) { whA[kk] = __half2half2(__ushort_as_half(0)); whB[kk] = whA[kk]; }
    float biasA = 0.f, wiA = 0.f, biasB = 0.f, wiB = 0.f;
    if (worker) {
        const int rowA = g * HID + jA;
        const float* wrA = Whh1 + rowA * HID;
        const float* wrB = isl2 ? (Wih2 + g * HID) : (Whh1 + (g * HID + jB) * HID);
#pragma unroll
        for (int kk = 0; kk < 26; kk++) {
            float a0 = wrA[2*kk];
            float a1 = (2*kk + 1 < HID) ? wrA[2*kk + 1] : 0.f;
            whA[kk] = __floats2half2_rn(a0, a1);
            float b0 = wrB[2*kk];
            float b1 = (2*kk + 1 < HID) ? wrB[2*kk + 1] : 0.f;
            whB[kk] = __floats2half2_rn(b0, b1);
        }
        biasA = bih1[rowA] + bhh1[rowA];
        wiA   = Wih1[rowA];
        if (isl2) { biasB = bih2[g] + bhh2[g]; wiB = Whh2[g]; }
        else {
            const int rowB = g * HID + jB;
            biasB = bih1[rowB] + bhh1[rowB];
            wiB   = Wih1[rowB];
        }
    }

    for (int i = tid; i < (int)(sizeof(hbuf) / 4); i += NTHREADS)
        ((unsigned*)hbuf)[i] = 0u;
    if (tid == 0) h2_sh = 0.f;

    float cstA = 0.f, cstB = 0.f;      // fp32 cell states (g0 lanes)

    // stage chunk 0 stimulus
    if (tid < 16) {
        *(float4*)&x_sh[tid * 4] = *(const float4*)&stim[n0 * TT + tid * 4];
    }
    __syncthreads();

#pragma unroll 1
    for (int t0 = 0; t0 < TT; t0 += CHUNK) {
#pragma unroll 2
        for (int dt = 0; dt < CHUNK; dt++) {
            const int rd = dt & 1;
            const float xt = x_sh[dt];
            const float xB = isl2 ? h2_sh : xt;
            const float baseA = fmaf(wiA, xt, biasA);
            const float baseB = fmaf(wiB, xB, biasB);

            // ---- dual-row matvec: shared h loads, fp16 HFMA2 -----------
            __half2 z = __half2half2(__ushort_as_half(0));
            __half2 a1A = z, a2A = z, a1B = z, a2B = z;
            const uint4* h4 = (const uint4*)&hbuf[rd][0];
#pragma unroll
            for (int q = 0; q < 6; q++) {          // pairs 0..23
                uint4 v = h4[q];
                __half2 h0 = *(__half2*)&v.x, h1 = *(__half2*)&v.y;
                __half2 h2v = *(__half2*)&v.z, h3 = *(__half2*)&v.w;
                a1A = __hfma2(whA[4*q + 0], h0, a1A);
                a2A = __hfma2(whA[4*q + 1], h1, a2A);
                a1B = __hfma2(whB[4*q + 0], h0, a1B);
                a2B = __hfma2(whB[4*q + 1], h1, a2B);
                a1A = __hfma2(whA[4*q + 2], h2v, a1A);
                a2A = __hfma2(whA[4*q + 3], h3, a2A);
                a1B = __hfma2(whB[4*q + 2], h2v, a1B);
                a2B = __hfma2(whB[4*q + 3], h3, a2B);
            }
            {                                       // pairs 24,25
                uint2 v = ((const uint2*)h4)[12];
                __half2 h0 = *(__half2*)&v.x, h1 = *(__half2*)&v.y;
                a1A = __hfma2(whA[24], h0, a1A);
                a2A = __hfma2(whA[25], h1, a2A);
                a1B = __hfma2(whB[24], h0, a1B);
                a2B = __hfma2(whB[25], h1, a2B);
            }
            float2 fA = __half22float2(__hadd2(a1A, a2A));
            float2 fB = __half22float2(__hadd2(a1B, a2B));
            float gA = fA.x + fA.y + baseA;
            float gB = fB.x + fB.y + baseB;

            // ---- activations -------------------------------------------
            float thA = tanhx(gg2 ? gA : 0.5f * gA);
            float thB = tanhx(gg2 ? gB : 0.5f * gB);
            float avA = gg2 ? thA : fmaf(0.5f, thA, 0.5f);
            float avB = gg2 ? thB : fmaf(0.5f, thB, 0.5f);

            // ---- gate exchange (nibble) + cell update ------------------
            float afA = __shfl_down_sync(0xFFFFFFFFu, avA, 1);
            float agA = __shfl_down_sync(0xFFFFFFFFu, avA, 2);
            float aoA = __shfl_down_sync(0xFFFFFFFFu, avA, 3);
            float afB = __shfl_down_sync(0xFFFFFFFFu, avB, 1);
            float agB = __shfl_down_sync(0xFFFFFFFFu, avB, 2);
            float aoB = __shfl_down_sync(0xFFFFFFFFu, avB, 3);
            if (g0 && worker) {
                cstA = fmaf(afA, cstA, avA * agA);
                float hA = aoA * tanhx(cstA);
                ((__half*)&hbuf[1 - rd][0])[jA] = __float2half_rn(hA);
                if (!isl2) {
                    cstB = fmaf(afB, cstB, avB * agB);
                    float hB = aoB * tanhx(cstB);
                    ((__half*)&hbuf[1 - rd][0])[jB] = __float2half_rn(hB);
                } else if ((t0 | dt) != 0) {
                    cstB = fmaf(afB, cstB, avB * agB);
                    float y = aoB * tanhx(cstB);
                    ob_sh[dt] = y;
                    h2_sh = y;
                }
            }
            __syncthreads();
        }
        // ---- flush outputs (lagged by 1) + stage next chunk ------------
        if (tid < 64) {
            int t = t0 - 1 + tid;
            if (t >= 0) out[n0 * TT + t] = ob_sh[tid];
        }
        if (t0 + CHUNK < TT && tid < 16) {
            *(float4*)&x_sh[tid * 4] =
                *(const float4*)&stim[n0 * TT + t0 + CHUNK + tid * 4];
        }
        __syncthreads();
    }

    // ---- tail: y(2047) from h1(2047) (in hbuf[0]) ----------------------
    if (wid == 3) {
        float baseB = fmaf(wiB, h2_sh, biasB);
        __half2 z = __half2half2(__ushort_as_half(0));
        __half2 a1B = z, a2B = z;
        const uint4* h4 = (const uint4*)&hbuf[0][0];
#pragma unroll
        for (int q = 0; q < 6; q++) {
            uint4 v = h4[q];
            a1B = __hfma2(whB[4*q + 0], *(__half2*)&v.x, a1B);
            a2B = __hfma2(whB[4*q + 1], *(__half2*)&v.y, a2B);
            a1B = __hfma2(whB[4*q + 2], *(__half2*)&v.z, a1B);
            a2B = __hfma2(whB[4*q + 3], *(__half2*)&v.w, a2B);
        }
        {
            uint2 v = ((const uint2*)h4)[12];
            a1B = __hfma2(whB[24], *(__half2*)&v.x, a1B);
            a2B = __hfma2(whB[25], *(__half2*)&v.y, a2B);
        }
        float2 fB = __half22float2(__hadd2(a1B, a2B));
        float gB = fB.x + fB.y + baseB;
        float thB = tanhx(gg2 ? gB : 0.5f * gB);
        float avB = gg2 ? thB : fmaf(0.5f, thB, 0.5f);
        float afB = __shfl_down_sync(0xFFFFFFFFu, avB, 1);
        float agB = __shfl_down_sync(0xFFFFFFFFu, avB, 2);
        float aoB = __shfl_down_sync(0xFFFFFFFFu, avB, 3);
        if (g0 && isl2) {
            cstB = fmaf(afB, cstB, avB * agB);
            out[n0 * TT + (TT - 1)] = aoB * tanhx(cstB);
        }
    }
}

extern "C" void kernel_launch(void* const* d_in, const int* in_sizes, int n_in,
                              void* d_out, int out_size)
{
    (void)in_sizes; (void)n_in; (void)out_size;
    const float* stim  = (const float*)d_in[0];
    const float* Wih1  = (const float*)d_in[1];
    const float* Whh1  = (const float*)d_in[2];
    const float* bih1  = (const float*)d_in[3];
    const float* bhh1  = (const float*)d_in[4];
    const float* Wih2  = (const float*)d_in[5];
    const float* Whh2  = (const float*)d_in[6];
    const float* bih2  = (const float*)d_in[7];
    const float* bhh2  = (const float*)d_in[8];
    float* out = (float*)d_out;

    lstm2_kernel<<<NN, NTHREADS>>>(stim, Wih1, Whh1, bih1, bhh1,
                                   Wih2, Whh2, bih2, bhh2, out);
}

// round 9
// speedup vs baseline: 1.9821x; 1.9821x over previous
#include <cuda_runtime.h>
#include <cuda_fp16.h>

#define HID   51
#define TT    2048
#define NN    1024
#define CHUNK 64
#define H2PAD 28          // half2 per h row (26 used + 2 pad) -> 112B, 16B-aligned
#define NTHREADS 64       // 2 warps; thread j = tid (j<51 layer-1, j==51 layer-2)

__device__ __forceinline__ float tanhx(float x) {
    float r; asm("tanh.approx.f32 %0, %1;" : "=f"(r) : "f"(x)); return r;
}

__global__ void __launch_bounds__(NTHREADS, 7)
lstm2_kernel(const float* __restrict__ stim,
             const float* __restrict__ Wih1,   // (204,1)
             const float* __restrict__ Whh1,   // (204,51)
             const float* __restrict__ bih1,
             const float* __restrict__ bhh1,
             const float* __restrict__ Wih2,   // (4,51)
             const float* __restrict__ Whh2,   // (4,1)
             const float* __restrict__ bih2,
             const float* __restrict__ bhh2,
             float* __restrict__ out)          // (1024,2048)
{
    __shared__ __align__(16) __half2 hbuf[2][H2PAD];   // h1(t) as fp16 pairs
    __shared__ __align__(16) float x_sh[CHUNK];
    __shared__ __align__(16) float ob_sh[CHUNK];       // y(t0+dt-1)

    const int tid = threadIdx.x;
    const int j   = tid;               // hidden unit; 51 => layer-2
    const int n0  = blockIdx.x;        // one sequence per block
    const bool worker = (j <= HID);
    const bool isl2   = (j == HID);

    // ---- all 4 gate rows of unit j in registers (fp16 pairs) ------------
    __half2 wh[4][26];
    float bias[4], wi[4];
#pragma unroll
    for (int gi = 0; gi < 4; gi++) {
        bias[gi] = 0.f; wi[gi] = 0.f;
#pragma unroll
        for (int kk = 0; kk < 26; kk++) wh[gi][kk] = __half2half2(__ushort_as_half(0));
    }
    if (worker) {
#pragma unroll
        for (int gi = 0; gi < 4; gi++) {
            const float* wr = isl2 ? (Wih2 + gi * HID)
                                   : (Whh1 + (gi * HID + j) * HID);
#pragma unroll
            for (int kk = 0; kk < 26; kk++) {
                float a = wr[2*kk];
                float b = (2*kk + 1 < HID) ? wr[2*kk + 1] : 0.f;
                wh[gi][kk] = __floats2half2_rn(a, b);
            }
            if (isl2) { bias[gi] = bih2[gi] + bhh2[gi]; wi[gi] = Whh2[gi]; }
            else {
                const int row = gi * HID + j;
                bias[gi] = bih1[row] + bhh1[row];
                wi[gi]   = Wih1[row];
            }
        }
    }

    for (int i = tid; i < (int)(sizeof(hbuf) / 4); i += NTHREADS)
        ((unsigned*)hbuf)[i] = 0u;

    float c = 0.f;                     // c1 (j<51) / c2 (j==51)
    float h2 = 0.f;                    // layer-2 hidden (j==51 only)

    if (tid < 16)
        *(float4*)&x_sh[tid * 4] = *(const float4*)&stim[n0 * TT + tid * 4];
    __syncthreads();

#pragma unroll 1
    for (int t0 = 0; t0 < TT; t0 += CHUNK) {
#pragma unroll 2
        for (int dt = 0; dt < CHUNK; dt++) {
            const int rd = dt & 1;
            const float xt  = x_sh[dt];
            const float xin = isl2 ? h2 : xt;

            // ---- 4-gate matvec over fp16 h (104 HFMA2) -----------------
            __half2 z = __half2half2(__ushort_as_half(0));
            __half2 a1[4] = {z, z, z, z};
            __half2 a2[4] = {z, z, z, z};
            const uint4* h4 = (const uint4*)&hbuf[rd][0];
#pragma unroll
            for (int q = 0; q < 6; q++) {          // pairs 0..23
                uint4 v = h4[q];
                __half2 h0 = *(__half2*)&v.x, h1 = *(__half2*)&v.y;
                __half2 hv2 = *(__half2*)&v.z, h3 = *(__half2*)&v.w;
#pragma unroll
                for (int gi = 0; gi < 4; gi++) {
                    a1[gi] = __hfma2(wh[gi][4*q + 0], h0,  a1[gi]);
                    a2[gi] = __hfma2(wh[gi][4*q + 1], h1,  a2[gi]);
                    a1[gi] = __hfma2(wh[gi][4*q + 2], hv2, a1[gi]);
                    a2[gi] = __hfma2(wh[gi][4*q + 3], h3,  a2[gi]);
                }
            }
            {                                       // pairs 24,25
                uint2 v = ((const uint2*)h4)[12];
                __half2 h0 = *(__half2*)&v.x, h1 = *(__half2*)&v.y;
#pragma unroll
                for (int gi = 0; gi < 4; gi++) {
                    a1[gi] = __hfma2(wh[gi][24], h0, a1[gi]);
                    a2[gi] = __hfma2(wh[gi][25], h1, a2[gi]);
                }
            }
            float gt[4];
#pragma unroll
            for (int gi = 0; gi < 4; gi++) {
                float2 f = __half22float2(__hadd2(a1[gi], a2[gi]));
                gt[gi] = f.x + f.y + fmaf(wi[gi], xin, bias[gi]);
            }
            // ---- activations + cell update (all in-thread) -------------
            float si = fmaf(0.5f, tanhx(0.5f * gt[0]), 0.5f);
            float sf = fmaf(0.5f, tanhx(0.5f * gt[1]), 0.5f);
            float tg = tanhx(gt[2]);
            float so = fmaf(0.5f, tanhx(0.5f * gt[3]), 0.5f);
            if (worker) {
                if (!isl2) {
                    c = fmaf(sf, c, si * tg);
                    float hv = so * tanhx(c);
                    ((__half*)&hbuf[1 - rd][0])[j] = __float2half_rn(hv);
                } else if ((t0 | dt) != 0) {       // y(t-1); skip spurious t=0
                    c = fmaf(sf, c, si * tg);
                    float y = so * tanhx(c);
                    ob_sh[dt] = y;
                    h2 = y;
                }
            }
            __syncthreads();
        }
        // ---- flush outputs (lagged by 1) + stage next chunk ------------
        {
            int t = t0 - 1 + tid;
            if (t >= 0) out[n0 * TT + t] = ob_sh[tid];
        }
        if (t0 + CHUNK < TT && tid < 16)
            *(float4*)&x_sh[tid * 4] =
                *(const float4*)&stim[n0 * TT + t0 + CHUNK + tid * 4];
        __syncthreads();
    }

    // ---- tail: y(2047) from h1(2047) (in hbuf[0]) ----------------------
    if (isl2) {
        __half2 z = __half2half2(__ushort_as_half(0));
        __half2 a1[4] = {z, z, z, z};
        __half2 a2[4] = {z, z, z, z};
        const uint4* h4 = (const uint4*)&hbuf[0][0];
#pragma unroll
        for (int q = 0; q < 6; q++) {
            uint4 v = h4[q];
#pragma unroll
            for (int gi = 0; gi < 4; gi++) {
                a1[gi] = __hfma2(wh[gi][4*q + 0], *(__half2*)&v.x, a1[gi]);
                a2[gi] = __hfma2(wh[gi][4*q + 1], *(__half2*)&v.y, a2[gi]);
                a1[gi] = __hfma2(wh[gi][4*q + 2], *(__half2*)&v.z, a1[gi]);
                a2[gi] = __hfma2(wh[gi][4*q + 3], *(__half2*)&v.w, a2[gi]);
            }
        }
        {
            uint2 v = ((const uint2*)h4)[12];
#pragma unroll
            for (int gi = 0; gi < 4; gi++) {
                a1[gi] = __hfma2(wh[gi][24], *(__half2*)&v.x, a1[gi]);
                a2[gi] = __hfma2(wh[gi][25], *(__half2*)&v.y, a2[gi]);
            }
        }
        float gt[4];
#pragma unroll
        for (int gi = 0; gi < 4; gi++) {
            float2 f = __half22float2(__hadd2(a1[gi], a2[gi]));
            gt[gi] = f.x + f.y + fmaf(wi[gi], h2, bias[gi]);
        }
        float si = fmaf(0.5f, tanhx(0.5f * gt[0]), 0.5f);
        float sf = fmaf(0.5f, tanhx(0.5f * gt[1]), 0.5f);
        float tg = tanhx(gt[2]);
        float so = fmaf(0.5f, tanhx(0.5f * gt[3]), 0.5f);
        c = fmaf(sf, c, si * tg);
        out[n0 * TT + (TT - 1)] = so * tanhx(c);
    }
}

extern "C" void kernel_launch(void* const* d_in, const int* in_sizes, int n_in,
                              void* d_out, int out_size)
{
    (void)in_sizes; (void)n_in; (void)out_size;
    const float* stim  = (const float*)d_in[0];
    const float* Wih1  = (const float*)d_in[1];
    const float* Whh1  = (const float*)d_in[2];
    const float* bih1  = (const float*)d_in[3];
    const float* bhh1  = (const float*)d_in[4];
    const float* Wih2  = (const float*)d_in[5];
    const float* Whh2  = (const float*)d_in[6];
    const float* bih2  = (const float*)d_in[7];
    const float* bhh2  = (const float*)d_in[8];
    float* out = (float*)d_out;

    lstm2_kernel<<<NN, NTHREADS>>>(stim, Wih1, Whh1, bih1, bhh1,
                                   Wih2, Whh2, bih2, bhh2, out);
}

// round 10
// speedup vs baseline: 1.9937x; 1.0058x over previous
#include <cuda_runtime.h>
#include <cuda_fp16.h>

#define HID   51
#define TT    2048
#define NN    1024
#define CHUNK 64
#define H2PAD 28          // half2 per h row (26 used + 2 pad) -> 112B
#define NTHREADS 64       // 2 warps; thread j = tid; 2 sequences per block

__device__ __forceinline__ float tanhx(float x) {
    float r; asm("tanh.approx.f32 %0, %1;" : "=f"(r) : "f"(x)); return r;
}

__global__ void __launch_bounds__(NTHREADS, 4)
lstm2_kernel(const float* __restrict__ stim,
             const float* __restrict__ Wih1,   // (204,1)
             const float* __restrict__ Whh1,   // (204,51)
             const float* __restrict__ bih1,
             const float* __restrict__ bhh1,
             const float* __restrict__ Wih2,   // (4,51)
             const float* __restrict__ Whh2,   // (4,1)
             const float* __restrict__ bih2,
             const float* __restrict__ bhh2,
             float* __restrict__ out)          // (1024,2048)
{
    __shared__ __align__(16) __half2 hbuf[2][2][H2PAD]; // [buf][seq][pair]
    __shared__ __align__(16) float x_sh[2][CHUNK];
    __shared__ __align__(16) float ob_sh[2][CHUNK];     // y(t0+dt-1)

    const int tid = threadIdx.x;
    const int j   = tid;               // hidden unit; 51 => layer-2
    const int n0  = blockIdx.x * 2;    // two sequences per block
    const bool worker = (j <= HID);
    const bool isl2   = (j == HID);

    // ---- all 4 gate rows of unit j in registers (fp16 pairs) ------------
    __half2 wh[4][26];
    float bias[4], wi[4];
#pragma unroll
    for (int gi = 0; gi < 4; gi++) {
        bias[gi] = 0.f; wi[gi] = 0.f;
#pragma unroll
        for (int kk = 0; kk < 26; kk++) wh[gi][kk] = __half2half2(__ushort_as_half(0));
    }
    if (worker) {
#pragma unroll
        for (int gi = 0; gi < 4; gi++) {
            const float* wr = isl2 ? (Wih2 + gi * HID)
                                   : (Whh1 + (gi * HID + j) * HID);
#pragma unroll
            for (int kk = 0; kk < 26; kk++) {
                float a = wr[2*kk];
                float b = (2*kk + 1 < HID) ? wr[2*kk + 1] : 0.f;
                wh[gi][kk] = __floats2half2_rn(a, b);
            }
            if (isl2) { bias[gi] = bih2[gi] + bhh2[gi]; wi[gi] = Whh2[gi]; }
            else {
                const int row = gi * HID + j;
                bias[gi] = bih1[row] + bhh1[row];
                wi[gi]   = Wih1[row];
            }
        }
    }

    for (int i = tid; i < (int)(sizeof(hbuf) / 4); i += NTHREADS)
        ((unsigned*)hbuf)[i] = 0u;

    float cA = 0.f, cB = 0.f;          // c1 (j<51) / c2 (j==51), per seq
    float h2A = 0.f, h2B = 0.f;        // layer-2 hidden (j==51 only)

    if (tid < 32) {
        int s = tid >> 4, q = (tid & 15) * 4;
        *(float4*)&x_sh[s][q] = *(const float4*)&stim[(n0 + s) * TT + q];
    }
    __syncthreads();

#pragma unroll 1
    for (int t0 = 0; t0 < TT; t0 += CHUNK) {
#pragma unroll 2
        for (int dt = 0; dt < CHUNK; dt++) {
            const int rd = dt & 1;
            const float xinA = isl2 ? h2A : x_sh[0][dt];
            const float xinB = isl2 ? h2B : x_sh[1][dt];

            // ---- dual-seq 4-gate matvec (208 HFMA2, shared weights) ----
            __half2 z = __half2half2(__ushort_as_half(0));
            __half2 a1A[4] = {z,z,z,z}, a2A[4] = {z,z,z,z};
            __half2 a1B[4] = {z,z,z,z}, a2B[4] = {z,z,z,z};
            const uint4* hA = (const uint4*)&hbuf[rd][0][0];
            const uint4* hB = (const uint4*)&hbuf[rd][1][0];
#pragma unroll
            for (int q = 0; q < 6; q++) {          // pairs 0..23
                uint4 vA = hA[q], vB = hB[q];
                __half2 hA0 = *(__half2*)&vA.x, hA1 = *(__half2*)&vA.y;
                __half2 hA2 = *(__half2*)&vA.z, hA3 = *(__half2*)&vA.w;
                __half2 hB0 = *(__half2*)&vB.x, hB1 = *(__half2*)&vB.y;
                __half2 hB2 = *(__half2*)&vB.z, hB3 = *(__half2*)&vB.w;
#pragma unroll
                for (int gi = 0; gi < 4; gi++) {
                    a1A[gi] = __hfma2(wh[gi][4*q + 0], hA0, a1A[gi]);
                    a1B[gi] = __hfma2(wh[gi][4*q + 0], hB0, a1B[gi]);
                    a2A[gi] = __hfma2(wh[gi][4*q + 1], hA1, a2A[gi]);
                    a2B[gi] = __hfma2(wh[gi][4*q + 1], hB1, a2B[gi]);
                    a1A[gi] = __hfma2(wh[gi][4*q + 2], hA2, a1A[gi]);
                    a1B[gi] = __hfma2(wh[gi][4*q + 2], hB2, a1B[gi]);
                    a2A[gi] = __hfma2(wh[gi][4*q + 3], hA3, a2A[gi]);
                    a2B[gi] = __hfma2(wh[gi][4*q + 3], hB3, a2B[gi]);
                }
            }
            {                                       // pairs 24,25
                uint2 vA = ((const uint2*)hA)[12], vB = ((const uint2*)hB)[12];
                __half2 hA0 = *(__half2*)&vA.x, hA1 = *(__half2*)&vA.y;
                __half2 hB0 = *(__half2*)&vB.x, hB1 = *(__half2*)&vB.y;
#pragma unroll
                for (int gi = 0; gi < 4; gi++) {
                    a1A[gi] = __hfma2(wh[gi][24], hA0, a1A[gi]);
                    a1B[gi] = __hfma2(wh[gi][24], hB0, a1B[gi]);
                    a2A[gi] = __hfma2(wh[gi][25], hA1, a2A[gi]);
                    a2B[gi] = __hfma2(wh[gi][25], hB1, a2B[gi]);
                }
            }
            float gtA[4], gtB[4];
#pragma unroll
            for (int gi = 0; gi < 4; gi++) {
                float2 fA = __half22float2(__hadd2(a1A[gi], a2A[gi]));
                float2 fB = __half22float2(__hadd2(a1B[gi], a2B[gi]));
                gtA[gi] = fA.x + fA.y + fmaf(wi[gi], xinA, bias[gi]);
                gtB[gi] = fB.x + fB.y + fmaf(wi[gi], xinB, bias[gi]);
            }
            // ---- activations + cell updates (both seqs, in-thread) -----
            float siA = fmaf(0.5f, tanhx(0.5f * gtA[0]), 0.5f);
            float sfA = fmaf(0.5f, tanhx(0.5f * gtA[1]), 0.5f);
            float tgA = tanhx(gtA[2]);
            float soA = fmaf(0.5f, tanhx(0.5f * gtA[3]), 0.5f);
            float siB = fmaf(0.5f, tanhx(0.5f * gtB[0]), 0.5f);
            float sfB = fmaf(0.5f, tanhx(0.5f * gtB[1]), 0.5f);
            float tgB = tanhx(gtB[2]);
            float soB = fmaf(0.5f, tanhx(0.5f * gtB[3]), 0.5f);
            if (worker) {
                if (!isl2) {
                    cA = fmaf(sfA, cA, siA * tgA);
                    cB = fmaf(sfB, cB, siB * tgB);
                    ((__half*)&hbuf[1 - rd][0][0])[j] = __float2half_rn(soA * tanhx(cA));
                    ((__half*)&hbuf[1 - rd][1][0])[j] = __float2half_rn(soB * tanhx(cB));
                } else if ((t0 | dt) != 0) {       // y(t-1); skip spurious t=0
                    cA = fmaf(sfA, cA, siA * tgA);
                    cB = fmaf(sfB, cB, siB * tgB);
                    float yA = soA * tanhx(cA);
                    float yB = soB * tanhx(cB);
                    ob_sh[0][dt] = yA; h2A = yA;
                    ob_sh[1][dt] = yB; h2B = yB;
                }
            }
            __syncthreads();
        }
        // ---- flush outputs (lagged by 1) + stage next chunk ------------
#pragma unroll
        for (int s = 0; s < 2; s++) {
            int t = t0 - 1 + tid;
            if (t >= 0) out[(n0 + s) * TT + t] = ob_sh[s][tid];
        }
        if (t0 + CHUNK < TT && tid < 32) {
            int s = tid >> 4, q = (tid & 15) * 4;
            *(float4*)&x_sh[s][q] =
                *(const float4*)&stim[(n0 + s) * TT + t0 + CHUNK + q];
        }
        __syncthreads();
    }

    // ---- tail: y(2047) for both seqs from h1(2047) (in hbuf[0]) --------
    if (isl2) {
        __half2 z = __half2half2(__ushort_as_half(0));
        __half2 a1A[4] = {z,z,z,z}, a2A[4] = {z,z,z,z};
        __half2 a1B[4] = {z,z,z,z}, a2B[4] = {z,z,z,z};
        const uint4* hA = (const uint4*)&hbuf[0][0][0];
        const uint4* hB = (const uint4*)&hbuf[0][1][0];
#pragma unroll
        for (int q = 0; q < 6; q++) {
            uint4 vA = hA[q], vB = hB[q];
#pragma unroll
            for (int gi = 0; gi < 4; gi++) {
                a1A[gi] = __hfma2(wh[gi][4*q + 0], *(__half2*)&vA.x, a1A[gi]);
                a2A[gi] = __hfma2(wh[gi][4*q + 1], *(__half2*)&vA.y, a2A[gi]);
                a1A[gi] = __hfma2(wh[gi][4*q + 2], *(__half2*)&vA.z, a1A[gi]);
                a2A[gi] = __hfma2(wh[gi][4*q + 3], *(__half2*)&vA.w, a2A[gi]);
                a1B[gi] = __hfma2(wh[gi][4*q + 0], *(__half2*)&vB.x, a1B[gi]);
                a2B[gi] = __hfma2(wh[gi][4*q + 1], *(__half2*)&vB.y, a2B[gi]);
                a1B[gi] = __hfma2(wh[gi][4*q + 2], *(__half2*)&vB.z, a1B[gi]);
                a2B[gi] = __hfma2(wh[gi][4*q + 3], *(__half2*)&vB.w, a2B[gi]);
            }
        }
        {
            uint2 vA = ((const uint2*)hA)[12], vB = ((const uint2*)hB)[12];
#pragma unroll
            for (int gi = 0; gi < 4; gi++) {
                a1A[gi] = __hfma2(wh[gi][24], *(__half2*)&vA.x, a1A[gi]);
                a2A[gi] = __hfma2(wh[gi][25], *(__half2*)&vA.y, a2A[gi]);
                a1B[gi] = __hfma2(wh[gi][24], *(__half2*)&vB.x, a1B[gi]);
                a2B[gi] = __hfma2(wh[gi][25], *(__half2*)&vB.y, a2B[gi]);
            }
        }
        float gtA[4], gtB[4];
#pragma unroll
        for (int gi = 0; gi < 4; gi++) {
            float2 fA = __half22float2(__hadd2(a1A[gi], a2A[gi]));
            float2 fB = __half22float2(__hadd2(a1B[gi], a2B[gi]));
            gtA[gi] = fA.x + fA.y + fmaf(wi[gi], h2A, bias[gi]);
            gtB[gi] = fB.x + fB.y + fmaf(wi[gi], h2B, bias[gi]);
        }
        cA = fmaf(fmaf(0.5f, tanhx(0.5f * gtA[1]), 0.5f), cA,
                  fmaf(0.5f, tanhx(0.5f * gtA[0]), 0.5f) * tanhx(gtA[2]));
        cB = fmaf(fmaf(0.5f, tanhx(0.5f * gtB[1]), 0.5f), cB,
                  fmaf(0.5f, tanhx(0.5f * gtB[0]), 0.5f) * tanhx(gtB[2]));
        out[(n0 + 0) * TT + (TT - 1)] =
            fmaf(0.5f, tanhx(0.5f * gtA[3]), 0.5f) * 2.0f * 0.5f * tanhx(cA) ;
        out[(n0 + 1) * TT + (TT - 1)] =
            fmaf(0.5f, tanhx(0.5f * gtB[3]), 0.5f) * 2.0f * 0.5f * tanhx(cB) ;
    }
}

extern "C" void kernel_launch(void* const* d_in, const int* in_sizes, int n_in,
                              void* d_out, int out_size)
{
    (void)in_sizes; (void)n_in; (void)out_size;
    const float* stim  = (const float*)d_in[0];
    const float* Wih1  = (const float*)d_in[1];
    const float* Whh1  = (const float*)d_in[2];
    const float* bih1  = (const float*)d_in[3];
    const float* bhh1  = (const float*)d_in[4];
    const float* Wih2  = (const float*)d_in[5];
    const float* Whh2  = (const float*)d_in[6];
    const float* bih2  = (const float*)d_in[7];
    const float* bhh2  = (const float*)d_in[8];
    float* out = (float*)d_out;

    lstm2_kernel<<<NN / 2, NTHREADS>>>(stim, Wih1, Whh1, bih1, bhh1,
                                       Wih2, Whh2, bih2, bhh2, out);
}

// round 11
// speedup vs baseline: 2.0159x; 1.0112x over previous
#include <cuda_runtime.h>
#include <cuda_fp16.h>

#define HID   51
#define TT    2048
#define NN    1024
#define CHUNK 64
#define H2PAD 28          // half2 per h row (26 used + 2 pad) -> 112B
#define NTHREADS 64       // 2 warps; thread j = tid; 2 sequences per block

__device__ __forceinline__ float tanhx(float x) {
    float r; asm("tanh.approx.f32 %0, %1;" : "=f"(r) : "f"(x)); return r;
}
// sum the two fp16 halves of a half2 (stays on fma pipe, no F2F)
__device__ __forceinline__ __half hsum2(__half2 v) {
    return __hadd(__low2half(v), __high2half(v));
}

__global__ void __launch_bounds__(NTHREADS, 4)
lstm2_kernel(const float* __restrict__ stim,
             const float* __restrict__ Wih1,   // (204,1)
             const float* __restrict__ Whh1,   // (204,51)
             const float* __restrict__ bih1,
             const float* __restrict__ bhh1,
             const float* __restrict__ Wih2,   // (4,51)
             const float* __restrict__ Whh2,   // (4,1)
             const float* __restrict__ bih2,
             const float* __restrict__ bhh2,
             float* __restrict__ out)          // (1024,2048)
{
    __shared__ __align__(16) __half2 hbuf[2][2][H2PAD]; // [buf][seq][pair]
    __shared__ __align__(16) float x_sh[2][CHUNK];
    __shared__ __align__(16) float ob_sh[2][CHUNK];     // y(t0+dt-1)

    const int tid = threadIdx.x;
    const int j   = tid;               // hidden unit; 51 => layer-2
    const int n0  = blockIdx.x * 2;    // two sequences per block
    const bool worker = (j <= HID);
    const bool isl2   = (j == HID);

    // ---- all 4 gate rows of unit j in registers (fp16 pairs) ------------
    __half2 wh[4][26];
    float bias[4], wi[4];
#pragma unroll
    for (int gi = 0; gi < 4; gi++) {
        bias[gi] = 0.f; wi[gi] = 0.f;
#pragma unroll
        for (int kk = 0; kk < 26; kk++) wh[gi][kk] = __half2half2(__ushort_as_half(0));
    }
    if (worker) {
#pragma unroll
        for (int gi = 0; gi < 4; gi++) {
            const float* wr = isl2 ? (Wih2 + gi * HID)
                                   : (Whh1 + (gi * HID + j) * HID);
#pragma unroll
            for (int kk = 0; kk < 26; kk++) {
                float a = wr[2*kk];
                float b = (2*kk + 1 < HID) ? wr[2*kk + 1] : 0.f;
                wh[gi][kk] = __floats2half2_rn(a, b);
            }
            if (isl2) { bias[gi] = bih2[gi] + bhh2[gi]; wi[gi] = Whh2[gi]; }
            else {
                const int row = gi * HID + j;
                bias[gi] = bih1[row] + bhh1[row];
                wi[gi]   = Wih1[row];
            }
        }
    }

    for (int i = tid; i < (int)(sizeof(hbuf) / 4); i += NTHREADS)
        ((unsigned*)hbuf)[i] = 0u;

    float cA = 0.f, cB = 0.f;          // c1 (j<51) / c2 (j==51), per seq
    float h2A = 0.f, h2B = 0.f;        // layer-2 hidden (j==51 only)

    if (tid < 32) {
        int s = tid >> 4, q = (tid & 15) * 4;
        *(float4*)&x_sh[s][q] = *(const float4*)&stim[(n0 + s) * TT + q];
    }
    __syncthreads();

#pragma unroll 1
    for (int t0 = 0; t0 < TT; t0 += CHUNK) {
#pragma unroll 2
        for (int dt = 0; dt < CHUNK; dt++) {
            const int rd = dt & 1;
            const float xinA = isl2 ? h2A : x_sh[0][dt];
            const float xinB = isl2 ? h2B : x_sh[1][dt];

            // ---- dual-seq 4-gate matvec (208 HFMA2, shared weights) ----
            __half2 z = __half2half2(__ushort_as_half(0));
            __half2 a1A[4] = {z,z,z,z}, a2A[4] = {z,z,z,z};
            __half2 a1B[4] = {z,z,z,z}, a2B[4] = {z,z,z,z};
            const uint4* hA = (const uint4*)&hbuf[rd][0][0];
            const uint4* hB = (const uint4*)&hbuf[rd][1][0];
#pragma unroll
            for (int q = 0; q < 6; q++) {          // pairs 0..23
                uint4 vA = hA[q], vB = hB[q];
                __half2 hA0 = *(__half2*)&vA.x, hA1 = *(__half2*)&vA.y;
                __half2 hA2 = *(__half2*)&vA.z, hA3 = *(__half2*)&vA.w;
                __half2 hB0 = *(__half2*)&vB.x, hB1 = *(__half2*)&vB.y;
                __half2 hB2 = *(__half2*)&vB.z, hB3 = *(__half2*)&vB.w;
#pragma unroll
                for (int gi = 0; gi < 4; gi++) {
                    a1A[gi] = __hfma2(wh[gi][4*q + 0], hA0, a1A[gi]);
                    a1B[gi] = __hfma2(wh[gi][4*q + 0], hB0, a1B[gi]);
                    a2A[gi] = __hfma2(wh[gi][4*q + 1], hA1, a2A[gi]);
                    a2B[gi] = __hfma2(wh[gi][4*q + 1], hB1, a2B[gi]);
                    a1A[gi] = __hfma2(wh[gi][4*q + 2], hA2, a1A[gi]);
                    a1B[gi] = __hfma2(wh[gi][4*q + 2], hB2, a1B[gi]);
                    a2A[gi] = __hfma2(wh[gi][4*q + 3], hA3, a2A[gi]);
                    a2B[gi] = __hfma2(wh[gi][4*q + 3], hB3, a2B[gi]);
                }
            }
            {                                       // pairs 24,25
                uint2 vA = ((const uint2*)hA)[12], vB = ((const uint2*)hB)[12];
                __half2 hA0 = *(__half2*)&vA.x, hA1 = *(__half2*)&vA.y;
                __half2 hB0 = *(__half2*)&vB.x, hB1 = *(__half2*)&vB.y;
#pragma unroll
                for (int gi = 0; gi < 4; gi++) {
                    a1A[gi] = __hfma2(wh[gi][24], hA0, a1A[gi]);
                    a1B[gi] = __hfma2(wh[gi][24], hB0, a1B[gi]);
                    a2A[gi] = __hfma2(wh[gi][25], hA1, a2A[gi]);
                    a2B[gi] = __hfma2(wh[gi][25], hB1, a2B[gi]);
                }
            }
            // ---- gate reduction: fp16 all the way, ONE cvt per gate ----
            float gtA[4], gtB[4];
#pragma unroll
            for (int gi = 0; gi < 4; gi++) {
                __half sA = hsum2(__hadd2(a1A[gi], a2A[gi]));
                __half sB = hsum2(__hadd2(a1B[gi], a2B[gi]));
                gtA[gi] = __half2float(sA) + fmaf(wi[gi], xinA, bias[gi]);
                gtB[gi] = __half2float(sB) + fmaf(wi[gi], xinB, bias[gi]);
            }
            // ---- activations + cell updates (both seqs, in-thread) -----
            float siA = fmaf(0.5f, tanhx(0.5f * gtA[0]), 0.5f);
            float sfA = fmaf(0.5f, tanhx(0.5f * gtA[1]), 0.5f);
            float tgA = tanhx(gtA[2]);
            float soA = fmaf(0.5f, tanhx(0.5f * gtA[3]), 0.5f);
            float siB = fmaf(0.5f, tanhx(0.5f * gtB[0]), 0.5f);
            float sfB = fmaf(0.5f, tanhx(0.5f * gtB[1]), 0.5f);
            float tgB = tanhx(gtB[2]);
            float soB = fmaf(0.5f, tanhx(0.5f * gtB[3]), 0.5f);
            if (worker) {
                if (!isl2) {
                    cA = fmaf(sfA, cA, siA * tgA);
                    cB = fmaf(sfB, cB, siB * tgB);
                    ((__half*)&hbuf[1 - rd][0][0])[j] = __float2half_rn(soA * tanhx(cA));
                    ((__half*)&hbuf[1 - rd][1][0])[j] = __float2half_rn(soB * tanhx(cB));
                } else if ((t0 | dt) != 0) {       // y(t-1); skip spurious t=0
                    cA = fmaf(sfA, cA, siA * tgA);
                    cB = fmaf(sfB, cB, siB * tgB);
                    float yA = soA * tanhx(cA);
                    float yB = soB * tanhx(cB);
                    ob_sh[0][dt] = yA; h2A = yA;
                    ob_sh[1][dt] = yB; h2B = yB;
                }
            }
            __syncthreads();
        }
        // ---- flush outputs (lagged by 1) + stage next chunk ------------
#pragma unroll
        for (int s = 0; s < 2; s++) {
            int t = t0 - 1 + tid;
            if (t >= 0) out[(n0 + s) * TT + t] = ob_sh[s][tid];
        }
        if (t0 + CHUNK < TT && tid < 32) {
            int s = tid >> 4, q = (tid & 15) * 4;
            *(float4*)&x_sh[s][q] =
                *(const float4*)&stim[(n0 + s) * TT + t0 + CHUNK + q];
        }
        __syncthreads();
    }

    // ---- tail: y(2047) for both seqs from h1(2047) (in hbuf[0]) --------
    if (isl2) {
        __half2 z = __half2half2(__ushort_as_half(0));
        __half2 a1A[4] = {z,z,z,z}, a2A[4] = {z,z,z,z};
        __half2 a1B[4] = {z,z,z,z}, a2B[4] = {z,z,z,z};
        const uint4* hA = (const uint4*)&hbuf[0][0][0];
        const uint4* hB = (const uint4*)&hbuf[0][1][0];
#pragma unroll
        for (int q = 0; q < 6; q++) {
            uint4 vA = hA[q], vB = hB[q];
#pragma unroll
            for (int gi = 0; gi < 4; gi++) {
                a1A[gi] = __hfma2(wh[gi][4*q + 0], *(__half2*)&vA.x, a1A[gi]);
                a2A[gi] = __hfma2(wh[gi][4*q + 1], *(__half2*)&vA.y, a2A[gi]);
                a1A[gi] = __hfma2(wh[gi][4*q + 2], *(__half2*)&vA.z, a1A[gi]);
                a2A[gi] = __hfma2(wh[gi][4*q + 3], *(__half2*)&vA.w, a2A[gi]);
                a1B[gi] = __hfma2(wh[gi][4*q + 0], *(__half2*)&vB.x, a1B[gi]);
                a2B[gi] = __hfma2(wh[gi][4*q + 1], *(__half2*)&vB.y, a2B[gi]);
                a1B[gi] = __hfma2(wh[gi][4*q + 2], *(__half2*)&vB.z, a1B[gi]);
                a2B[gi] = __hfma2(wh[gi][4*q + 3], *(__half2*)&vB.w, a2B[gi]);
            }
        }
        {
            uint2 vA = ((const uint2*)hA)[12], vB = ((const uint2*)hB)[12];
#pragma unroll
            for (int gi = 0; gi < 4; gi++) {
                a1A[gi] = __hfma2(wh[gi][24], *(__half2*)&vA.x, a1A[gi]);
                a2A[gi] = __hfma2(wh[gi][25], *(__half2*)&vA.y, a2A[gi]);
                a1B[gi] = __hfma2(wh[gi][24], *(__half2*)&vB.x, a1B[gi]);
                a2B[gi] = __hfma2(wh[gi][25], *(__half2*)&vB.y, a2B[gi]);
            }
        }
        float gtA[4], gtB[4];
#pragma unroll
        for (int gi = 0; gi < 4; gi++) {
            __half sA = hsum2(__hadd2(a1A[gi], a2A[gi]));
            __half sB = hsum2(__hadd2(a1B[gi], a2B[gi]));
            gtA[gi] = __half2float(sA) + fmaf(wi[gi], h2A, bias[gi]);
            gtB[gi] = __half2float(sB) + fmaf(wi[gi], h2B, bias[gi]);
        }
        cA = fmaf(fmaf(0.5f, tanhx(0.5f * gtA[1]), 0.5f), cA,
                  fmaf(0.5f, tanhx(0.5f * gtA[0]), 0.5f) * tanhx(gtA[2]));
        cB = fmaf(fmaf(0.5f, tanhx(0.5f * gtB[1]), 0.5f), cB,
                  fmaf(0.5f, tanhx(0.5f * gtB[0]), 0.5f) * tanhx(gtB[2]));
        out[(n0 + 0) * TT + (TT - 1)] =
            fmaf(0.5f, tanhx(0.5f * gtA[3]), 0.5f) * tanhx(cA);
        out[(n0 + 1) * TT + (TT - 1)] =
            fmaf(0.5f, tanhx(0.5f * gtB[3]), 0.5f) * tanhx(cB);
    }
}

extern "C" void kernel_launch(void* const* d_in, const int* in_sizes, int n_in,
                              void* d_out, int out_size)
{
    (void)in_sizes; (void)n_in; (void)out_size;
    const float* stim  = (const float*)d_in[0];
    const float* Wih1  = (const float*)d_in[1];
    const float* Whh1  = (const float*)d_in[2];
    const float* bih1  = (const float*)d_in[3];
    const float* bhh1  = (const float*)d_in[4];
    const float* Wih2  = (const float*)d_in[5];
    const float* Whh2  = (const float*)d_in[6];
    const float* bih2  = (const float*)d_in[7];
    const float* bhh2  = (const float*)d_in[8];
    float* out = (float*)d_out;

    lstm2_kernel<<<NN / 2, NTHREADS>>>(stim, Wih1, Whh1, bih1, bhh1,
                                       Wih2, Whh2, bih2, bhh2, out);
}

// round 12
// speedup vs baseline: 2.0416x; 1.0127x over previous
#include <cuda_runtime.h>
#include <cuda_fp16.h>

#define HID   51
#define TT    2048
#define NN    1024
#define CHUNK 64
#define NTHREADS 32       // ONE warp per block; thread t owns units t and t+32

__device__ __forceinline__ float tanhx(float x) {
    float r; asm("tanh.approx.f32 %0, %1;" : "=f"(r) : "f"(x)); return r;
}
__device__ __forceinline__ __half hsum2(__half2 v) {
    return __hadd(__low2half(v), __high2half(v));
}

__global__ void __launch_bounds__(NTHREADS)
lstm2_kernel(const float* __restrict__ stim,
             const float* __restrict__ Wih1,   // (204,1)
             const float* __restrict__ Whh1,   // (204,51)
             const float* __restrict__ bih1,
             const float* __restrict__ bhh1,
             const float* __restrict__ Wih2,   // (4,51)
             const float* __restrict__ Whh2,   // (4,1)
             const float* __restrict__ bih2,
             const float* __restrict__ bhh2,
             float* __restrict__ out)          // (1024,2048)
{
    __shared__ __align__(16) __half hbuf[2][56];   // h1 fp16; [51..55] zero pad
    __shared__ __align__(16) float x_sh[CHUNK];
    __shared__ __align__(16) float ob_sh[CHUNK];   // y(t0+dt-1)

    const int tid = threadIdx.x;
    const int n0  = blockIdx.x;        // one sequence per block
    const int uA  = tid;               // unit A: 0..31
    const int uB  = tid + 32;          // unit B: 32..51 (tid<20)
    const bool hasB = (uB <= HID);
    const bool isl2 = (uB == HID);     // tid == 19 -> unit 51 = layer-2

    // ---- weights: 2 units x 4 gates in fp16 pairs (208 regs) ------------
    __half2 whA[4][26], whB[4][26];
    float biasA[4], wiA[4], biasB[4], wiB[4];
#pragma unroll
    for (int gi = 0; gi < 4; gi++) {
        const int rowA = gi * HID + uA;
        const float* wrA = Whh1 + rowA * HID;
#pragma unroll
        for (int kk = 0; kk < 26; kk++) {
            float a = wrA[2*kk];
            float b = (2*kk + 1 < HID) ? wrA[2*kk + 1] : 0.f;
            whA[gi][kk] = __floats2half2_rn(a, b);
        }
        biasA[gi] = bih1[rowA] + bhh1[rowA];
        wiA[gi]   = Wih1[rowA];

        biasB[gi] = 0.f; wiB[gi] = 0.f;
#pragma unroll
        for (int kk = 0; kk < 26; kk++) whB[gi][kk] = __half2half2(__ushort_as_half(0));
        if (hasB) {
            const float* wrB = isl2 ? (Wih2 + gi * HID)
                                    : (Whh1 + (gi * HID + uB) * HID);
#pragma unroll
            for (int kk = 0; kk < 26; kk++) {
                float a = wrB[2*kk];
                float b = (2*kk + 1 < HID) ? wrB[2*kk + 1] : 0.f;
                whB[gi][kk] = __floats2half2_rn(a, b);
            }
            if (isl2) { biasB[gi] = bih2[gi] + bhh2[gi]; wiB[gi] = Whh2[gi]; }
            else {
                const int rowB = gi * HID + uB;
                biasB[gi] = bih1[rowB] + bhh1[rowB];
                wiB[gi]   = Wih1[rowB];
            }
        }
    }

    // zero h buffers (pads stay zero forever)
    for (int i = tid; i < 56; i += NTHREADS) {
        ((unsigned*)hbuf)[i] = 0u;     // covers 2*56 halfs as 56 u32
    }
    float cA = 0.f, cB = 0.f;          // fp32 cell states (unit A / unit B|L2)
    float h2 = 0.f;                    // layer-2 hidden (thread 19 only)

    if (tid < 16)
        *(float4*)&x_sh[tid * 4] = *(const float4*)&stim[n0 * TT + tid * 4];
    __syncwarp();

#pragma unroll 1
    for (int t0 = 0; t0 < TT; t0 += CHUNK) {
#pragma unroll 2
        for (int dt = 0; dt < CHUNK; dt++) {
            const int rd = dt & 1;
            const float xt  = x_sh[dt];
            const float xB  = isl2 ? h2 : xt;

            // ---- 8 gate chains over fp16 h (208 HFMA2) -----------------
            __half2 z = __half2half2(__ushort_as_half(0));
            __half2 aA[4] = {z, z, z, z};
            __half2 aB[4] = {z, z, z, z};
            const uint4* h4 = (const uint4*)&hbuf[rd][0];
#pragma unroll
            for (int q = 0; q < 6; q++) {          // pairs 0..23
                uint4 v = h4[q];
                __half2 h0 = *(__half2*)&v.x, h1 = *(__half2*)&v.y;
                __half2 hv2 = *(__half2*)&v.z, h3 = *(__half2*)&v.w;
#pragma unroll
                for (int gi = 0; gi < 4; gi++) {
                    aA[gi] = __hfma2(whA[gi][4*q + 0], h0,  aA[gi]);
                    aB[gi] = __hfma2(whB[gi][4*q + 0], h0,  aB[gi]);
                    aA[gi] = __hfma2(whA[gi][4*q + 1], h1,  aA[gi]);
                    aB[gi] = __hfma2(whB[gi][4*q + 1], h1,  aB[gi]);
                    aA[gi] = __hfma2(whA[gi][4*q + 2], hv2, aA[gi]);
                    aB[gi] = __hfma2(whB[gi][4*q + 2], hv2, aB[gi]);
                    aA[gi] = __hfma2(whA[gi][4*q + 3], h3,  aA[gi]);
                    aB[gi] = __hfma2(whB[gi][4*q + 3], h3,  aB[gi]);
                }
            }
            {                                       // pairs 24,25
                uint2 v = ((const uint2*)h4)[12];
                __half2 h0 = *(__half2*)&v.x, h1 = *(__half2*)&v.y;
#pragma unroll
                for (int gi = 0; gi < 4; gi++) {
                    aA[gi] = __hfma2(whA[gi][24], h0, aA[gi]);
                    aB[gi] = __hfma2(whB[gi][24], h0, aB[gi]);
                    aA[gi] = __hfma2(whA[gi][25], h1, aA[gi]);
                    aB[gi] = __hfma2(whB[gi][25], h1, aB[gi]);
                }
            }
            float gtA[4], gtB[4];
#pragma unroll
            for (int gi = 0; gi < 4; gi++) {
                gtA[gi] = __half2float(hsum2(aA[gi])) + fmaf(wiA[gi], xt, biasA[gi]);
                gtB[gi] = __half2float(hsum2(aB[gi])) + fmaf(wiB[gi], xB, biasB[gi]);
            }
            // ---- activations + cell updates (fully in-thread) ----------
            float siA = fmaf(0.5f, tanhx(0.5f * gtA[0]), 0.5f);
            float sfA = fmaf(0.5f, tanhx(0.5f * gtA[1]), 0.5f);
            float tgA = tanhx(gtA[2]);
            float soA = fmaf(0.5f, tanhx(0.5f * gtA[3]), 0.5f);
            cA = fmaf(sfA, cA, siA * tgA);
            hbuf[1 - rd][uA] = __float2half_rn(soA * tanhx(cA));

            if (hasB) {
                float siB = fmaf(0.5f, tanhx(0.5f * gtB[0]), 0.5f);
                float sfB = fmaf(0.5f, tanhx(0.5f * gtB[1]), 0.5f);
                float tgB = tanhx(gtB[2]);
                float soB = fmaf(0.5f, tanhx(0.5f * gtB[3]), 0.5f);
                if (!isl2) {
                    cB = fmaf(sfB, cB, siB * tgB);
                    hbuf[1 - rd][uB] = __float2half_rn(soB * tanhx(cB));
                } else if ((t0 | dt) != 0) {       // layer-2, lag-1; skip t=0
                    cB = fmaf(sfB, cB, siB * tgB);
                    float y = soB * tanhx(cB);
                    ob_sh[dt] = y;
                    h2 = y;
                }
            }
            __syncwarp();
        }
        // ---- flush outputs (lagged by 1) + stage next chunk ------------
        for (int i = tid; i < CHUNK; i += NTHREADS) {
            int t = t0 - 1 + i;
            if (t >= 0) out[n0 * TT + t] = ob_sh[i];
        }
        if (t0 + CHUNK < TT && tid < 16)
            *(float4*)&x_sh[tid * 4] =
                *(const float4*)&stim[n0 * TT + t0 + CHUNK + tid * 4];
        __syncwarp();
    }

    // ---- tail: y(2047) from h1(2047) (in hbuf[0]); thread 19 only ------
    if (isl2) {
        __half2 z = __half2half2(__ushort_as_half(0));
        __half2 aB[4] = {z, z, z, z};
        const uint4* h4 = (const uint4*)&hbuf[0][0];
#pragma unroll
        for (int q = 0; q < 6; q++) {
            uint4 v = h4[q];
#pragma unroll
            for (int gi = 0; gi < 4; gi++) {
                aB[gi] = __hfma2(whB[gi][4*q + 0], *(__half2*)&v.x, aB[gi]);
                aB[gi] = __hfma2(whB[gi][4*q + 1], *(__half2*)&v.y, aB[gi]);
                aB[gi] = __hfma2(whB[gi][4*q + 2], *(__half2*)&v.z, aB[gi]);
                aB[gi] = __hfma2(whB[gi][4*q + 3], *(__half2*)&v.w, aB[gi]);
            }
        }
        {
            uint2 v = ((const uint2*)h4)[12];
#pragma unroll
            for (int gi = 0; gi < 4; gi++) {
                aB[gi] = __hfma2(whB[gi][24], *(__half2*)&v.x, aB[gi]);
                aB[gi] = __hfma2(whB[gi][25], *(__half2*)&v.y, aB[gi]);
            }
        }
        float gtB[4];
#pragma unroll
        for (int gi = 0; gi < 4; gi++)
            gtB[gi] = __half2float(hsum2(aB[gi])) + fmaf(wiB[gi], h2, biasB[gi]);
        float siB = fmaf(0.5f, tanhx(0.5f * gtB[0]), 0.5f);
        float sfB = fmaf(0.5f, tanhx(0.5f * gtB[1]), 0.5f);
        float tgB = tanhx(gtB[2]);
        float soB = fmaf(0.5f, tanhx(0.5f * gtB[3]), 0.5f);
        cB = fmaf(sfB, cB, siB * tgB);
        out[n0 * TT + (TT - 1)] = soB * tanhx(cB);
    }
}

extern "C" void kernel_launch(void* const* d_in, const int* in_sizes, int n_in,
                              void* d_out, int out_size)
{
    (void)in_sizes; (void)n_in; (void)out_size;
    const float* stim  = (const float*)d_in[0];
    const float* Wih1  = (const float*)d_in[1];
    const float* Whh1  = (const float*)d_in[2];
    const float* bih1  = (const float*)d_in[3];
    const float* bhh1  = (const float*)d_in[4];
    const float* Wih2  = (const float*)d_in[5];
    const float* Whh2  = (const float*)d_in[6];
    const float* bih2  = (const float*)d_in[7];
    const float* bhh2  = (const float*)d_in[8];
    float* out = (float*)d_out;

    lstm2_kernel<<<NN, NTHREADS>>>(stim, Wih1, Whh1, bih1, bhh1,
                                   Wih2, Whh2, bih2, bhh2, out);
}